// round 2
// baseline (speedup 1.0000x reference)
#include <cuda_runtime.h>
#include <cstdint>

#define NN 100000
#define NE 1600000
#define DIN 128
#define DH 64
#define NG 512

// ---------------- scratch (device globals; no allocation allowed) -------------
__device__ float g_u1[NN * DH];    // x @ W1_l
__device__ float g_t1[NN * DH];    // x @ W1_r + b1
__device__ float g_acc1[NN * DH];  // segment_sum over edges of u1[src]
__device__ float g_h[NN * DH];     // relu(acc1/deg + t1)
__device__ float g_acc2[NN * DH];  // segment_sum over edges of h[src]
__device__ float g_deg[NN];
__device__ float g_Sm[NG * DH];    // per-graph sum of mean2
__device__ float g_Sh[NG * DH];    // per-graph sum of h
__device__ float g_cnt[NG];

// ---------------- helpers ----------------------------------------------------
__device__ __forceinline__ void red4(float* a, float4 v) {
    asm volatile("red.global.add.v4.f32 [%0], {%1,%2,%3,%4};"
                 :: "l"(a), "f"(v.x), "f"(v.y), "f"(v.z), "f"(v.w) : "memory");
}
__device__ __forceinline__ void red1(float* a, float v) {
    asm volatile("red.global.add.f32 [%0], %1;" :: "l"(a), "f"(v) : "memory");
}

// ---------------- kernels ----------------------------------------------------
__global__ void zero_kernel() {
    int i = blockIdx.x * blockDim.x + threadIdx.x;
    if (i < NN * DH) { g_acc1[i] = 0.f; g_acc2[i] = 0.f; }
    if (i < NN)      g_deg[i] = 0.f;
    if (i < NG * DH) { g_Sm[i] = 0.f; g_Sh[i] = 0.f; }
    if (i < NG)      g_cnt[i] = 0.f;
}

// u1 = x @ W1_l ; t1 = x @ W1_r + b1.  Combined as one N x 128 x 128 GEMM.
// Block: 128 rows x 128 cols, 256 threads, TM=8 x TN=8 register tile.
__global__ __launch_bounds__(256) void gemm1_kernel(
    const float* __restrict__ x, const float* __restrict__ Wl,
    const float* __restrict__ Wr, const float* __restrict__ b1)
{
    __shared__ float Xs[128][33];   // [row][k], padded to kill bank conflicts
    __shared__ float Ws[32][128];   // [k][col] (col<64 -> Wl, col>=64 -> Wr)

    const int tid = threadIdx.x;
    const int ty = tid >> 4;        // 0..15 -> 8-row group
    const int tx = tid & 15;        // 0..15 -> col = tx + 16*j
    const int row0 = blockIdx.x * 128;

    float acc[8][8];
#pragma unroll
    for (int r = 0; r < 8; r++)
#pragma unroll
        for (int j = 0; j < 8; j++) acc[r][j] = 0.f;

    for (int k0 = 0; k0 < DIN; k0 += 32) {
        // load X tile (128 rows x 32 k), coalesced float4
#pragma unroll
        for (int p = 0; p < 4; p++) {
            int i = tid + p * 256;          // 0..1023
            int row = i >> 3;               // 0..127
            int kq  = i & 7;                // 0..7 (float4 within 32 k)
            float4 v = make_float4(0.f, 0.f, 0.f, 0.f);
            if (row0 + row < NN)
                v = *reinterpret_cast<const float4*>(
                        x + (size_t)(row0 + row) * DIN + k0 + kq * 4);
            Xs[row][kq * 4 + 0] = v.x;
            Xs[row][kq * 4 + 1] = v.y;
            Xs[row][kq * 4 + 2] = v.z;
            Xs[row][kq * 4 + 3] = v.w;
        }
        // load W tile (32 k x 128 cols)
#pragma unroll
        for (int p = 0; p < 4; p++) {
            int i = tid + p * 256;          // 0..1023
            int k = i >> 5;                 // 0..31
            int n = (i & 31) * 4;           // 0..124
            const float* sp = (n < DH) ? (Wl + (size_t)(k0 + k) * DH + n)
                                       : (Wr + (size_t)(k0 + k) * DH + (n - DH));
            *reinterpret_cast<float4*>(&Ws[k][n]) =
                *reinterpret_cast<const float4*>(sp);
        }
        __syncthreads();

#pragma unroll
        for (int k = 0; k < 32; k++) {
            float a[8], b[8];
#pragma unroll
            for (int r = 0; r < 8; r++) a[r] = Xs[ty * 8 + r][k];
#pragma unroll
            for (int j = 0; j < 8; j++) b[j] = Ws[k][tx + 16 * j];
#pragma unroll
            for (int r = 0; r < 8; r++)
#pragma unroll
                for (int j = 0; j < 8; j++) acc[r][j] += a[r] * b[j];
        }
        __syncthreads();
    }

#pragma unroll
    for (int r = 0; r < 8; r++) {
        int row = row0 + ty * 8 + r;
        if (row >= NN) continue;
#pragma unroll
        for (int j = 0; j < 8; j++) {
            int col = tx + 16 * j;
            if (col < DH) g_u1[(size_t)row * DH + col] = acc[r][j];
            else          g_t1[(size_t)row * DH + (col - DH)] = acc[r][j] + b1[col - DH];
        }
    }
}

// Edge aggregation: 16 lanes per edge, one float4 gather + one red.v4 each.
// layer==1: u1 -> acc1 (+deg); layer==2: h -> acc2.
__global__ __launch_bounds__(256) void agg_kernel(
    const int* __restrict__ es, const int* __restrict__ ed, int layer)
{
    int t = blockIdx.x * blockDim.x + threadIdx.x;
    int e = t >> 4;
    int lane = t & 15;
    if (e >= NE) return;
    int s = es[e];
    int d = ed[e];
    const float* feat = (layer == 1) ? g_u1 : g_h;
    float* acc        = (layer == 1) ? g_acc1 : g_acc2;
    float4 v = *reinterpret_cast<const float4*>(feat + (size_t)s * DH + lane * 4);
    red4(acc + (size_t)d * DH + lane * 4, v);
    if (layer == 1 && lane == 0) red1(g_deg + d, 1.0f);
}

// h = relu(acc1/max(deg,1) + t1)
__global__ __launch_bounds__(256) void relu_kernel() {
    int i = blockIdx.x * blockDim.x + threadIdx.x;   // float4 index
    if (i >= NN * (DH / 4)) return;
    int row = i >> 4;                                 // /16 float4 per row
    float inv = 1.0f / fmaxf(g_deg[row], 1.0f);
    float4 a = reinterpret_cast<const float4*>(g_acc1)[i];
    float4 t = reinterpret_cast<const float4*>(g_t1)[i];
    float4 h;
    h.x = fmaxf(fmaf(a.x, inv, t.x), 0.f);
    h.y = fmaxf(fmaf(a.y, inv, t.y), 0.f);
    h.z = fmaxf(fmaf(a.z, inv, t.z), 0.f);
    h.w = fmaxf(fmaf(a.w, inv, t.w), 0.f);
    reinterpret_cast<float4*>(g_h)[i] = h;
}

// Per-graph sums exploiting sorted batch_index: register run accumulation,
// atomics only at run boundaries. 128 threads: 64 for Sh (h), 64 for Sm (mean2).
__global__ __launch_bounds__(128) void pool_kernel(const int* __restrict__ batch) {
    const int n0 = blockIdx.x * 128;
    const int nend = min(n0 + 128, NN);
    const int tid = threadIdx.x;
    const int c = tid & 63;
    const int which = tid >> 6;     // 0 -> Sh, 1 -> Sm

    float local = 0.f;
    float cntloc = 0.f;
    int gcur = batch[n0];

    for (int n = n0; n < nend; n++) {
        int g = batch[n];
        if (g != gcur) {
            if (which == 0) red1(&g_Sh[gcur * DH + c], local);
            else            red1(&g_Sm[gcur * DH + c], local);
            if (tid == 0)   red1(&g_cnt[gcur], cntloc);
            local = 0.f; cntloc = 0.f; gcur = g;
        }
        float v;
        if (which == 0) v = g_h[(size_t)n * DH + c];
        else            v = g_acc2[(size_t)n * DH + c] / fmaxf(g_deg[n], 1.0f);
        local += v;
        cntloc += 1.f;
    }
    if (which == 0) red1(&g_Sh[gcur * DH + c], local);
    else            red1(&g_Sm[gcur * DH + c], local);
    if (tid == 0)   red1(&g_cnt[gcur], cntloc);
}

// out[g] = (Sm[g] @ W2_l + Sh[g] @ W2_r) / cnt[g] + b2
__global__ __launch_bounds__(128) void final_kernel(
    const float* __restrict__ W2l, const float* __restrict__ W2r,
    const float* __restrict__ b2, float* __restrict__ out)
{
    __shared__ float sm[DH], sh[DH];
    int g = blockIdx.x;
    int tid = threadIdx.x;
    if (tid < DH) {
        sm[tid] = g_Sm[g * DH + tid];
        sh[tid] = g_Sh[g * DH + tid];
    }
    __syncthreads();
    float a = 0.f;
#pragma unroll
    for (int k = 0; k < DH; k++) {
        a = fmaf(sm[k], W2l[(size_t)k * 128 + tid], a);
        a = fmaf(sh[k], W2r[(size_t)k * 128 + tid], a);
    }
    out[(size_t)g * 128 + tid] = a / fmaxf(g_cnt[g], 1.0f) + b2[tid];
}

// ---------------- launch ------------------------------------------------------
extern "C" void kernel_launch(void* const* d_in, const int* in_sizes, int n_in,
                              void* d_out, int out_size)
{
    const float* x    = (const float*)d_in[0];
    const float* W1l  = (const float*)d_in[1];
    const float* W1r  = (const float*)d_in[2];
    const float* b1   = (const float*)d_in[3];
    const float* W2l  = (const float*)d_in[4];
    const float* W2r  = (const float*)d_in[5];
    const float* b2   = (const float*)d_in[6];
    const int*   eidx = (const int*)d_in[7];     // int32: JAX x64 is disabled
    const int*   batch= (const int*)d_in[8];
    float* out = (float*)d_out;

    const int* es = eidx;         // edge_index[0]
    const int* ed = eidx + NE;    // edge_index[1]

    zero_kernel<<<(NN * DH + 255) / 256, 256>>>();
    gemm1_kernel<<<(NN + 127) / 128, 256>>>(x, W1l, W1r, b1);
    agg_kernel<<<(NE * 16 + 255) / 256, 256>>>(es, ed, 1);
    relu_kernel<<<(NN * (DH / 4) + 255) / 256, 256>>>();
    agg_kernel<<<(NE * 16 + 255) / 256, 256>>>(es, ed, 2);
    pool_kernel<<<(NN + 127) / 128, 128>>>(batch);
    final_kernel<<<NG, 128>>>(W2l, W2r, b2, out);
}

// round 4
// speedup vs baseline: 1.0208x; 1.0208x over previous
#include <cuda_runtime.h>
#include <cstdint>

#define NN 100000
#define NE 1600000
#define DIN 128
#define DH 64
#define NG 512
#define NB 391            // ceil(NN/256)

// ---------------- scratch (device globals) ------------------------------------
__device__ float g_u1[NN * DH];    // x @ W1_l
__device__ float g_t1[NN * DH];    // x @ W1_r + b1
__device__ float g_h[NN * DH];     // layer-1 output
__device__ float g_m2[NN * DH];    // layer-2 mean-aggregated neighbors
__device__ float g_invdeg[NN];
__device__ int   g_degn[NN];       // per-node in-degree (histogram)
__device__ int   g_off[NN];        // CSR row offsets
__device__ int   g_cur[NN];        // fill cursors
__device__ int   g_csr[NE];        // CSR column (src) ids
__device__ int   g_bsum[NB];
__device__ int   g_bbase[NB];
__device__ float g_Sm[NG * DH];    // per-graph sum of mean2
__device__ float g_Sh[NG * DH];    // per-graph sum of h
__device__ float g_cnt[NG];

__device__ __forceinline__ void red1(float* a, float v) {
    asm volatile("red.global.add.f32 [%0], %1;" :: "l"(a), "f"(v) : "memory");
}

// ---------------- CSR construction --------------------------------------------
// Grid MUST cover NN (stale g_degn on graph replay otherwise!)
__global__ void zero_kernel() {
    int i = blockIdx.x * blockDim.x + threadIdx.x;
    if (i < NN)      g_degn[i] = 0;
    if (i < NG * DH) { g_Sm[i] = 0.f; g_Sh[i] = 0.f; }
    if (i < NG)      g_cnt[i] = 0.f;
}

__global__ __launch_bounds__(256) void hist_kernel(const int* __restrict__ ed) {
    int e = blockIdx.x * blockDim.x + threadIdx.x;
    if (e < NE) atomicAdd(&g_degn[ed[e]], 1);
}

__global__ __launch_bounds__(256) void scan1_kernel() {
    __shared__ int sh[256];
    int n = blockIdx.x * 256 + threadIdx.x;
    int c = (n < NN) ? g_degn[n] : 0;
    sh[threadIdx.x] = c; __syncthreads();
    for (int d = 128; d > 0; d >>= 1) {
        if (threadIdx.x < d) sh[threadIdx.x] += sh[threadIdx.x + d];
        __syncthreads();
    }
    if (threadIdx.x == 0) g_bsum[blockIdx.x] = sh[0];
}

__global__ __launch_bounds__(512) void scan2_kernel() {
    __shared__ int sh[512];
    int tid = threadIdx.x;
    int v = (tid < NB) ? g_bsum[tid] : 0;
    sh[tid] = v; __syncthreads();
    for (int d = 1; d < 512; d <<= 1) {
        int t = (tid >= d) ? sh[tid - d] : 0;
        __syncthreads();
        sh[tid] += t;
        __syncthreads();
    }
    if (tid < NB) g_bbase[tid] = sh[tid] - v;   // exclusive
}

__global__ __launch_bounds__(256) void scan3_kernel() {
    __shared__ int sh[256];
    int tid = threadIdx.x;
    int n = blockIdx.x * 256 + tid;
    int c = (n < NN) ? g_degn[n] : 0;
    sh[tid] = c; __syncthreads();
    for (int d = 1; d < 256; d <<= 1) {
        int t = (tid >= d) ? sh[tid - d] : 0;
        __syncthreads();
        sh[tid] += t;
        __syncthreads();
    }
    if (n < NN) {
        int off = g_bbase[blockIdx.x] + sh[tid] - c;   // exclusive within grid
        g_off[n] = off;
        g_cur[n] = off;
        g_invdeg[n] = 1.0f / (float)max(c, 1);
    }
}

__global__ __launch_bounds__(256) void fill_kernel(
    const int* __restrict__ es, const int* __restrict__ ed) {
    int e = blockIdx.x * blockDim.x + threadIdx.x;
    if (e >= NE) return;
    int pos = atomicAdd(&g_cur[ed[e]], 1);
    g_csr[pos] = es[e];
}

// ---------------- GEMM: u1 = x@W1_l ; t1 = x@W1_r + b1 -------------------------
__global__ __launch_bounds__(256) void gemm1_kernel(
    const float* __restrict__ x, const float* __restrict__ Wl,
    const float* __restrict__ Wr, const float* __restrict__ b1)
{
    __shared__ float Xs[128][33];
    __shared__ float Ws[32][128];

    const int tid = threadIdx.x;
    const int ty = tid >> 4;
    const int tx = tid & 15;
    const int row0 = blockIdx.x * 128;

    float acc[8][8];
#pragma unroll
    for (int r = 0; r < 8; r++)
#pragma unroll
        for (int j = 0; j < 8; j++) acc[r][j] = 0.f;

    for (int k0 = 0; k0 < DIN; k0 += 32) {
#pragma unroll
        for (int p = 0; p < 4; p++) {
            int i = tid + p * 256;
            int row = i >> 3;
            int kq  = i & 7;
            float4 v = make_float4(0.f, 0.f, 0.f, 0.f);
            if (row0 + row < NN)
                v = *reinterpret_cast<const float4*>(
                        x + (size_t)(row0 + row) * DIN + k0 + kq * 4);
            Xs[row][kq * 4 + 0] = v.x;
            Xs[row][kq * 4 + 1] = v.y;
            Xs[row][kq * 4 + 2] = v.z;
            Xs[row][kq * 4 + 3] = v.w;
        }
#pragma unroll
        for (int p = 0; p < 4; p++) {
            int i = tid + p * 256;
            int k = i >> 5;
            int n = (i & 31) * 4;
            const float* sp = (n < DH) ? (Wl + (size_t)(k0 + k) * DH + n)
                                       : (Wr + (size_t)(k0 + k) * DH + (n - DH));
            *reinterpret_cast<float4*>(&Ws[k][n]) =
                *reinterpret_cast<const float4*>(sp);
        }
        __syncthreads();

#pragma unroll
        for (int k = 0; k < 32; k++) {
            float a[8], b[8];
#pragma unroll
            for (int r = 0; r < 8; r++) a[r] = Xs[ty * 8 + r][k];
#pragma unroll
            for (int j = 0; j < 8; j++) b[j] = Ws[k][tx + 16 * j];
#pragma unroll
            for (int r = 0; r < 8; r++)
#pragma unroll
                for (int j = 0; j < 8; j++) acc[r][j] += a[r] * b[j];
        }
        __syncthreads();
    }

#pragma unroll
    for (int r = 0; r < 8; r++) {
        int row = row0 + ty * 8 + r;
        if (row >= NN) continue;
#pragma unroll
        for (int j = 0; j < 8; j++) {
            int col = tx + 16 * j;
            if (col < DH) g_u1[(size_t)row * DH + col] = acc[r][j];
            else          g_t1[(size_t)row * DH + (col - DH)] = acc[r][j] + b1[col - DH];
        }
    }
}

// ---------------- pull aggregation (CSR), fused epilogues ----------------------
__device__ __forceinline__ void acc4(float4& s, const float4& v) {
    s.x += v.x; s.y += v.y; s.z += v.z; s.w += v.w;
}

__global__ __launch_bounds__(256) void agg1_kernel() {
    int t = blockIdx.x * blockDim.x + threadIdx.x;
    int n = t >> 4;
    int lane = t & 15;
    if (n >= NN) return;
    int off = g_off[n];
    int deg = g_degn[n];
    const int* __restrict__ lst = g_csr + off;

    float4 s = make_float4(0.f, 0.f, 0.f, 0.f);
    int j = 0;
    for (; j + 4 <= deg; j += 4) {
        int s0 = lst[j], s1 = lst[j + 1], s2 = lst[j + 2], s3 = lst[j + 3];
        float4 v0 = *reinterpret_cast<const float4*>(g_u1 + (size_t)s0 * DH + lane * 4);
        float4 v1 = *reinterpret_cast<const float4*>(g_u1 + (size_t)s1 * DH + lane * 4);
        float4 v2 = *reinterpret_cast<const float4*>(g_u1 + (size_t)s2 * DH + lane * 4);
        float4 v3 = *reinterpret_cast<const float4*>(g_u1 + (size_t)s3 * DH + lane * 4);
        acc4(s, v0); acc4(s, v1); acc4(s, v2); acc4(s, v3);
    }
    for (; j < deg; j++) {
        int sj = lst[j];
        float4 v = *reinterpret_cast<const float4*>(g_u1 + (size_t)sj * DH + lane * 4);
        acc4(s, v);
    }
    float inv = g_invdeg[n];
    float4 tt = *reinterpret_cast<const float4*>(g_t1 + (size_t)n * DH + lane * 4);
    float4 h;
    h.x = fmaxf(fmaf(s.x, inv, tt.x), 0.f);
    h.y = fmaxf(fmaf(s.y, inv, tt.y), 0.f);
    h.z = fmaxf(fmaf(s.z, inv, tt.z), 0.f);
    h.w = fmaxf(fmaf(s.w, inv, tt.w), 0.f);
    *reinterpret_cast<float4*>(g_h + (size_t)n * DH + lane * 4) = h;
}

__global__ __launch_bounds__(256) void agg2_kernel() {
    int t = blockIdx.x * blockDim.x + threadIdx.x;
    int n = t >> 4;
    int lane = t & 15;
    if (n >= NN) return;
    int off = g_off[n];
    int deg = g_degn[n];
    const int* __restrict__ lst = g_csr + off;

    float4 s = make_float4(0.f, 0.f, 0.f, 0.f);
    int j = 0;
    for (; j + 4 <= deg; j += 4) {
        int s0 = lst[j], s1 = lst[j + 1], s2 = lst[j + 2], s3 = lst[j + 3];
        float4 v0 = *reinterpret_cast<const float4*>(g_h + (size_t)s0 * DH + lane * 4);
        float4 v1 = *reinterpret_cast<const float4*>(g_h + (size_t)s1 * DH + lane * 4);
        float4 v2 = *reinterpret_cast<const float4*>(g_h + (size_t)s2 * DH + lane * 4);
        float4 v3 = *reinterpret_cast<const float4*>(g_h + (size_t)s3 * DH + lane * 4);
        acc4(s, v0); acc4(s, v1); acc4(s, v2); acc4(s, v3);
    }
    for (; j < deg; j++) {
        int sj = lst[j];
        float4 v = *reinterpret_cast<const float4*>(g_h + (size_t)sj * DH + lane * 4);
        acc4(s, v);
    }
    float inv = g_invdeg[n];
    float4 m;
    m.x = s.x * inv; m.y = s.y * inv; m.z = s.z * inv; m.w = s.w * inv;
    *reinterpret_cast<float4*>(g_m2 + (size_t)n * DH + lane * 4) = m;
}

// ---------------- pooling (sorted batch_index, run-length accumulate) ----------
__global__ __launch_bounds__(128) void pool_kernel(const int* __restrict__ batch) {
    const int n0 = blockIdx.x * 128;
    const int nend = min(n0 + 128, NN);
    const int tid = threadIdx.x;
    const int c = tid & 63;
    const int which = tid >> 6;     // 0 -> Sh (h), 1 -> Sm (m2)

    float local = 0.f;
    float cntloc = 0.f;
    int gcur = batch[n0];

    for (int n = n0; n < nend; n++) {
        int g = batch[n];
        if (g != gcur) {
            if (which == 0) red1(&g_Sh[gcur * DH + c], local);
            else            red1(&g_Sm[gcur * DH + c], local);
            if (tid == 0)   red1(&g_cnt[gcur], cntloc);
            local = 0.f; cntloc = 0.f; gcur = g;
        }
        float v = (which == 0) ? g_h[(size_t)n * DH + c]
                               : g_m2[(size_t)n * DH + c];
        local += v;
        cntloc += 1.f;
    }
    if (which == 0) red1(&g_Sh[gcur * DH + c], local);
    else            red1(&g_Sm[gcur * DH + c], local);
    if (tid == 0)   red1(&g_cnt[gcur], cntloc);
}

// out[g] = (Sm[g] @ W2_l + Sh[g] @ W2_r) / cnt[g] + b2
__global__ __launch_bounds__(128) void final_kernel(
    const float* __restrict__ W2l, const float* __restrict__ W2r,
    const float* __restrict__ b2, float* __restrict__ out)
{
    __shared__ float sm[DH], sh[DH];
    int g = blockIdx.x;
    int tid = threadIdx.x;
    if (tid < DH) {
        sm[tid] = g_Sm[g * DH + tid];
        sh[tid] = g_Sh[g * DH + tid];
    }
    __syncthreads();
    float a = 0.f;
#pragma unroll
    for (int k = 0; k < DH; k++) {
        a = fmaf(sm[k], W2l[(size_t)k * 128 + tid], a);
        a = fmaf(sh[k], W2r[(size_t)k * 128 + tid], a);
    }
    out[(size_t)g * 128 + tid] = a / fmaxf(g_cnt[g], 1.0f) + b2[tid];
}

// ---------------- launch ------------------------------------------------------
extern "C" void kernel_launch(void* const* d_in, const int* in_sizes, int n_in,
                              void* d_out, int out_size)
{
    const float* x    = (const float*)d_in[0];
    const float* W1l  = (const float*)d_in[1];
    const float* W1r  = (const float*)d_in[2];
    const float* b1   = (const float*)d_in[3];
    const float* W2l  = (const float*)d_in[4];
    const float* W2r  = (const float*)d_in[5];
    const float* b2   = (const float*)d_in[6];
    const int*   eidx = (const int*)d_in[7];     // int32 (JAX x64 disabled)
    const int*   batch= (const int*)d_in[8];
    float* out = (float*)d_out;

    const int* es = eidx;         // edge_index[0] (src)
    const int* ed = eidx + NE;    // edge_index[1] (dst)

    zero_kernel<<<(NN + 255) / 256, 256>>>();          // covers NN > NG*DH
    hist_kernel<<<(NE + 255) / 256, 256>>>(ed);
    scan1_kernel<<<NB, 256>>>();
    scan2_kernel<<<1, 512>>>();
    scan3_kernel<<<NB, 256>>>();
    fill_kernel<<<(NE + 255) / 256, 256>>>(es, ed);
    gemm1_kernel<<<(NN + 127) / 128, 256>>>(x, W1l, W1r, b1);
    agg1_kernel<<<(NN * 16 + 255) / 256, 256>>>();
    agg2_kernel<<<(NN * 16 + 255) / 256, 256>>>();
    pool_kernel<<<(NN + 127) / 128, 128>>>(batch);
    final_kernel<<<NG, 128>>>(W2l, W2r, b2, out);
}

// round 5
// speedup vs baseline: 1.6064x; 1.5737x over previous
#include <cuda_runtime.h>
#include <cstdint>

#define NN 100000
#define NE 1600000
#define DIN 128
#define DH 64
#define NG 512
#define NB 391            // ceil(NN/256)

// ---------------- scratch (device globals) ------------------------------------
__device__ float g_u1[NN * DH];    // x @ W1_l
__device__ float g_t1[NN * DH];    // x @ W1_r + b1
__device__ float g_h[NN * DH];     // layer-1 output
__device__ float g_m2[NN * DH];    // layer-2 mean-aggregated neighbors
__device__ float g_invdeg[NN];
__device__ int   g_degn[NN];       // per-node in-degree
__device__ int   g_off[NN];        // CSR row offsets
__device__ int   g_cur[NN];        // fill cursors
__device__ int   g_csr[NE];        // CSR column (src) ids
__device__ int   g_total;          // running base for block offsets
__device__ float g_Sm[NG * DH];    // per-graph sum of mean2
__device__ float g_Sh[NG * DH];    // per-graph sum of h
__device__ float g_cnt[NG];

__device__ __forceinline__ void red1(float* a, float v) {
    asm volatile("red.global.add.f32 [%0], %1;" :: "l"(a), "f"(v) : "memory");
}
__device__ __forceinline__ unsigned long long pack_dup(float a) {
    unsigned long long r;
    unsigned int ai = __float_as_uint(a);
    asm("mov.b64 %0, {%1, %1};" : "=l"(r) : "r"(ai));
    return r;
}
__device__ __forceinline__ void ffma2(unsigned long long& d,
                                      unsigned long long a, unsigned long long b) {
    asm("fma.rn.f32x2 %0, %1, %2, %0;" : "+l"(d) : "l"(a), "l"(b));
}
__device__ __forceinline__ void unpack2(unsigned long long p, float& x, float& y) {
    unsigned int lo, hi;
    asm("mov.b64 {%0, %1}, %2;" : "=r"(lo), "=r"(hi) : "l"(p));
    x = __uint_as_float(lo); y = __uint_as_float(hi);
}

// ---------------- CSR construction --------------------------------------------
__global__ void zero_kernel() {
    int i = blockIdx.x * blockDim.x + threadIdx.x;
    if (i < NN)      g_degn[i] = 0;
    if (i < NG * DH) { g_Sm[i] = 0.f; g_Sh[i] = 0.f; }
    if (i < NG)      g_cnt[i] = 0.f;
    if (i == 0)      g_total = 0;
}

__global__ __launch_bounds__(256) void hist_kernel(const int* __restrict__ ed) {
    int e = blockIdx.x * blockDim.x + threadIdx.x;
    if (e < NE) atomicAdd(&g_degn[ed[e]], 1);
}

// Block-local exclusive scan + atomic block base (ranges disjoint; order free).
__global__ __launch_bounds__(256) void scan_kernel() {
    __shared__ int sh[256];
    __shared__ int base_sh;
    int tid = threadIdx.x;
    int n = blockIdx.x * 256 + tid;
    int c = (n < NN) ? g_degn[n] : 0;
    sh[tid] = c; __syncthreads();
    for (int d = 1; d < 256; d <<= 1) {
        int t = (tid >= d) ? sh[tid - d] : 0;
        __syncthreads();
        sh[tid] += t;
        __syncthreads();
    }
    if (tid == 255) base_sh = atomicAdd(&g_total, sh[255]);
    __syncthreads();
    if (n < NN) {
        int off = base_sh + sh[tid] - c;   // exclusive within block + base
        g_off[n] = off;
        g_cur[n] = off;
        g_invdeg[n] = 1.0f / (float)max(c, 1);
    }
}

__global__ __launch_bounds__(256) void fill_kernel(
    const int* __restrict__ es, const int* __restrict__ ed) {
    int e = blockIdx.x * blockDim.x + threadIdx.x;
    if (e >= NE) return;
    int pos = atomicAdd(&g_cur[ed[e]], 1);
    g_csr[pos] = es[e];
}

// ---------------- GEMM (packed f32x2): u1 = x@W1_l ; t1 = x@W1_r + b1 ----------
// 128x128 block tile, 256 threads. Thread tile: 8 rows x 4 col-PAIRS.
// Thread cols: {tx*2 + 32*jj, tx*2+1 + 32*jj}, jj=0..3. Pairs never straddle
// the u1/t1 boundary (col 64).
__global__ __launch_bounds__(256) void gemm1_kernel(
    const float* __restrict__ x, const float* __restrict__ Wl,
    const float* __restrict__ Wr, const float* __restrict__ b1)
{
    __shared__ float Xs[128][33];
    __shared__ float Ws[32][128];

    const int tid = threadIdx.x;
    const int ty = tid >> 4;        // 0..15 (8-row group)
    const int tx = tid & 15;        // 0..15 (col pair base)
    const int row0 = blockIdx.x * 128;

    unsigned long long acc[8][4];
#pragma unroll
    for (int r = 0; r < 8; r++)
#pragma unroll
        for (int j = 0; j < 4; j++) acc[r][j] = 0ull;   // (0.f, 0.f)

    for (int k0 = 0; k0 < DIN; k0 += 32) {
#pragma unroll
        for (int p = 0; p < 4; p++) {
            int i = tid + p * 256;
            int row = i >> 3;
            int kq  = i & 7;
            float4 v = make_float4(0.f, 0.f, 0.f, 0.f);
            if (row0 + row < NN)
                v = *reinterpret_cast<const float4*>(
                        x + (size_t)(row0 + row) * DIN + k0 + kq * 4);
            Xs[row][kq * 4 + 0] = v.x;
            Xs[row][kq * 4 + 1] = v.y;
            Xs[row][kq * 4 + 2] = v.z;
            Xs[row][kq * 4 + 3] = v.w;
        }
#pragma unroll
        for (int p = 0; p < 4; p++) {
            int i = tid + p * 256;
            int k = i >> 5;
            int n = (i & 31) * 4;
            const float* sp = (n < DH) ? (Wl + (size_t)(k0 + k) * DH + n)
                                       : (Wr + (size_t)(k0 + k) * DH + (n - DH));
            *reinterpret_cast<float4*>(&Ws[k][n]) =
                *reinterpret_cast<const float4*>(sp);
        }
        __syncthreads();

#pragma unroll
        for (int k = 0; k < 32; k++) {
            unsigned long long bp[4];
#pragma unroll
            for (int jj = 0; jj < 4; jj++)
                bp[jj] = *reinterpret_cast<const unsigned long long*>(
                             &Ws[k][tx * 2 + 32 * jj]);
#pragma unroll
            for (int r = 0; r < 8; r++) {
                unsigned long long ap = pack_dup(Xs[ty * 8 + r][k]);
                ffma2(acc[r][0], ap, bp[0]);
                ffma2(acc[r][1], ap, bp[1]);
                ffma2(acc[r][2], ap, bp[2]);
                ffma2(acc[r][3], ap, bp[3]);
            }
        }
        __syncthreads();
    }

#pragma unroll
    for (int r = 0; r < 8; r++) {
        int row = row0 + ty * 8 + r;
        if (row >= NN) continue;
#pragma unroll
        for (int jj = 0; jj < 4; jj++) {
            int c = tx * 2 + 32 * jj;
            float v0, v1; unpack2(acc[r][jj], v0, v1);
            if (c < DH) {
                float2 o = make_float2(v0, v1);
                *reinterpret_cast<float2*>(g_u1 + (size_t)row * DH + c) = o;
            } else {
                int cc = c - DH;
                float2 o = make_float2(v0 + b1[cc], v1 + b1[cc + 1]);
                *reinterpret_cast<float2*>(g_t1 + (size_t)row * DH + cc) = o;
            }
        }
    }
}

// ---------------- pull aggregation (CSR), fused epilogues ----------------------
__device__ __forceinline__ void acc4(float4& s, const float4& v) {
    s.x += v.x; s.y += v.y; s.z += v.z; s.w += v.w;
}

__global__ __launch_bounds__(256) void agg1_kernel() {
    int t = blockIdx.x * blockDim.x + threadIdx.x;
    int n = t >> 4;
    int lane = t & 15;
    if (n >= NN) return;
    int off = g_off[n];
    int deg = g_degn[n];
    const int* __restrict__ lst = g_csr + off;

    float4 s = make_float4(0.f, 0.f, 0.f, 0.f);
    int j = 0;
    for (; j + 8 <= deg; j += 8) {
        int i0 = lst[j],     i1 = lst[j + 1], i2 = lst[j + 2], i3 = lst[j + 3];
        int i4 = lst[j + 4], i5 = lst[j + 5], i6 = lst[j + 6], i7 = lst[j + 7];
        float4 v0 = *reinterpret_cast<const float4*>(g_u1 + (size_t)i0 * DH + lane * 4);
        float4 v1 = *reinterpret_cast<const float4*>(g_u1 + (size_t)i1 * DH + lane * 4);
        float4 v2 = *reinterpret_cast<const float4*>(g_u1 + (size_t)i2 * DH + lane * 4);
        float4 v3 = *reinterpret_cast<const float4*>(g_u1 + (size_t)i3 * DH + lane * 4);
        float4 v4 = *reinterpret_cast<const float4*>(g_u1 + (size_t)i4 * DH + lane * 4);
        float4 v5 = *reinterpret_cast<const float4*>(g_u1 + (size_t)i5 * DH + lane * 4);
        float4 v6 = *reinterpret_cast<const float4*>(g_u1 + (size_t)i6 * DH + lane * 4);
        float4 v7 = *reinterpret_cast<const float4*>(g_u1 + (size_t)i7 * DH + lane * 4);
        acc4(s, v0); acc4(s, v1); acc4(s, v2); acc4(s, v3);
        acc4(s, v4); acc4(s, v5); acc4(s, v6); acc4(s, v7);
    }
    for (; j < deg; j++) {
        float4 v = *reinterpret_cast<const float4*>(g_u1 + (size_t)lst[j] * DH + lane * 4);
        acc4(s, v);
    }
    float inv = g_invdeg[n];
    float4 tt = *reinterpret_cast<const float4*>(g_t1 + (size_t)n * DH + lane * 4);
    float4 h;
    h.x = fmaxf(fmaf(s.x, inv, tt.x), 0.f);
    h.y = fmaxf(fmaf(s.y, inv, tt.y), 0.f);
    h.z = fmaxf(fmaf(s.z, inv, tt.z), 0.f);
    h.w = fmaxf(fmaf(s.w, inv, tt.w), 0.f);
    *reinterpret_cast<float4*>(g_h + (size_t)n * DH + lane * 4) = h;
}

__global__ __launch_bounds__(256) void agg2_kernel() {
    int t = blockIdx.x * blockDim.x + threadIdx.x;
    int n = t >> 4;
    int lane = t & 15;
    if (n >= NN) return;
    int off = g_off[n];
    int deg = g_degn[n];
    const int* __restrict__ lst = g_csr + off;

    float4 s = make_float4(0.f, 0.f, 0.f, 0.f);
    int j = 0;
    for (; j + 8 <= deg; j += 8) {
        int i0 = lst[j],     i1 = lst[j + 1], i2 = lst[j + 2], i3 = lst[j + 3];
        int i4 = lst[j + 4], i5 = lst[j + 5], i6 = lst[j + 6], i7 = lst[j + 7];
        float4 v0 = *reinterpret_cast<const float4*>(g_h + (size_t)i0 * DH + lane * 4);
        float4 v1 = *reinterpret_cast<const float4*>(g_h + (size_t)i1 * DH + lane * 4);
        float4 v2 = *reinterpret_cast<const float4*>(g_h + (size_t)i2 * DH + lane * 4);
        float4 v3 = *reinterpret_cast<const float4*>(g_h + (size_t)i3 * DH + lane * 4);
        float4 v4 = *reinterpret_cast<const float4*>(g_h + (size_t)i4 * DH + lane * 4);
        float4 v5 = *reinterpret_cast<const float4*>(g_h + (size_t)i5 * DH + lane * 4);
        float4 v6 = *reinterpret_cast<const float4*>(g_h + (size_t)i6 * DH + lane * 4);
        float4 v7 = *reinterpret_cast<const float4*>(g_h + (size_t)i7 * DH + lane * 4);
        acc4(s, v0); acc4(s, v1); acc4(s, v2); acc4(s, v3);
        acc4(s, v4); acc4(s, v5); acc4(s, v6); acc4(s, v7);
    }
    for (; j < deg; j++) {
        float4 v = *reinterpret_cast<const float4*>(g_h + (size_t)lst[j] * DH + lane * 4);
        acc4(s, v);
    }
    float inv = g_invdeg[n];
    float4 m;
    m.x = s.x * inv; m.y = s.y * inv; m.z = s.z * inv; m.w = s.w * inv;
    *reinterpret_cast<float4*>(g_m2 + (size_t)n * DH + lane * 4) = m;
}

// ---------------- pooling (sorted batch_index, run-length accumulate) ----------
__global__ __launch_bounds__(128) void pool_kernel(const int* __restrict__ batch) {
    const int n0 = blockIdx.x * 128;
    const int nend = min(n0 + 128, NN);
    const int tid = threadIdx.x;
    const int c = tid & 63;
    const int which = tid >> 6;     // 0 -> Sh (h), 1 -> Sm (m2)

    float local = 0.f;
    float cntloc = 0.f;
    int gcur = batch[n0];

    for (int n = n0; n < nend; n++) {
        int g = batch[n];
        if (g != gcur) {
            if (which == 0) red1(&g_Sh[gcur * DH + c], local);
            else            red1(&g_Sm[gcur * DH + c], local);
            if (tid == 0)   red1(&g_cnt[gcur], cntloc);
            local = 0.f; cntloc = 0.f; gcur = g;
        }
        float v = (which == 0) ? g_h[(size_t)n * DH + c]
                               : g_m2[(size_t)n * DH + c];
        local += v;
        cntloc += 1.f;
    }
    if (which == 0) red1(&g_Sh[gcur * DH + c], local);
    else            red1(&g_Sm[gcur * DH + c], local);
    if (tid == 0)   red1(&g_cnt[gcur], cntloc);
}

// out[g] = (Sm[g] @ W2_l + Sh[g] @ W2_r) / cnt[g] + b2
__global__ __launch_bounds__(128) void final_kernel(
    const float* __restrict__ W2l, const float* __restrict__ W2r,
    const float* __restrict__ b2, float* __restrict__ out)
{
    __shared__ float sm[DH], sh[DH];
    int g = blockIdx.x;
    int tid = threadIdx.x;
    if (tid < DH) {
        sm[tid] = g_Sm[g * DH + tid];
        sh[tid] = g_Sh[g * DH + tid];
    }
    __syncthreads();
    float a = 0.f;
#pragma unroll
    for (int k = 0; k < DH; k++) {
        a = fmaf(sm[k], W2l[(size_t)k * 128 + tid], a);
        a = fmaf(sh[k], W2r[(size_t)k * 128 + tid], a);
    }
    out[(size_t)g * 128 + tid] = a / fmaxf(g_cnt[g], 1.0f) + b2[tid];
}

// ---------------- launch ------------------------------------------------------
// Launch order chosen so ncu (-s 5 -c 1) captures agg1_kernel (index 5).
extern "C" void kernel_launch(void* const* d_in, const int* in_sizes, int n_in,
                              void* d_out, int out_size)
{
    const float* x    = (const float*)d_in[0];
    const float* W1l  = (const float*)d_in[1];
    const float* W1r  = (const float*)d_in[2];
    const float* b1   = (const float*)d_in[3];
    const float* W2l  = (const float*)d_in[4];
    const float* W2r  = (const float*)d_in[5];
    const float* b2   = (const float*)d_in[6];
    const int*   eidx = (const int*)d_in[7];     // int32 (JAX x64 disabled)
    const int*   batch= (const int*)d_in[8];
    float* out = (float*)d_out;

    const int* es = eidx;         // edge_index[0] (src)
    const int* ed = eidx + NE;    // edge_index[1] (dst)

    zero_kernel<<<(NN + 255) / 256, 256>>>();                 // 0
    hist_kernel<<<(NE + 255) / 256, 256>>>(ed);               // 1
    scan_kernel<<<NB, 256>>>();                               // 2
    fill_kernel<<<(NE + 255) / 256, 256>>>(es, ed);           // 3
    gemm1_kernel<<<(NN + 127) / 128, 256>>>(x, W1l, W1r, b1); // 4
    agg1_kernel<<<(NN * 16 + 255) / 256, 256>>>();            // 5  <- ncu -s 5
    agg2_kernel<<<(NN * 16 + 255) / 256, 256>>>();            // 6
    pool_kernel<<<(NN + 127) / 128, 128>>>(batch);            // 7
    final_kernel<<<NG, 128>>>(W2l, W2r, b2, out);             // 8
}